// round 3
// baseline (speedup 1.0000x reference)
#include <cuda_runtime.h>

#define N 8192
#define ROWS_PER_BLK 32
#define COLS_PER_BLK 2048
#define CB 4      /* column tiles: 8192/2048 */
#define RB 256    /* row tiles:    8192/32   */
#define THREADS 256
#define NBLK2 32  /* combine blocks */

// Scratch (no device allocation allowed -> __device__ globals)
__device__ float g_rowpart[CB * N];     // [cb][row]   partial row sums
__device__ float g_colpart[RB * N];     // [rb][col]   partial col sums (8 MiB)
__device__ float g_blocksum[NBLK2];     // combine block partials

// ---------------------------------------------------------------------------
// Pass 1: one block per 32x2048 tile (1024 blocks). Streaming single read of
// the 256 MiB matrix. Loop body has NO cross-lane dependency: per-row scalar
// partials go to smem (1 STS) and are reduced once after the loop.
// ---------------------------------------------------------------------------
__global__ void __launch_bounds__(THREADS)
tile_kernel(const float* __restrict__ flow)
{
    const int cb   = blockIdx.x;          // 0..3
    const int rb   = blockIdx.y;          // 0..255
    const int t    = threadIdx.x;         // 0..255
    const int row0 = rb * ROWS_PER_BLK;
    const int col0 = cb * COLS_PER_BLK;

    __shared__ float s_part[ROWS_PER_BLK][THREADS];   // 32 KB

    // Thread t owns float4 columns {t, t+256} within the tile -> 8 scalar cols
    float4 c0 = make_float4(0.f, 0.f, 0.f, 0.f);
    float4 c1 = make_float4(0.f, 0.f, 0.f, 0.f);

    const float4* base = reinterpret_cast<const float4*>(flow)
                         + (size_t)row0 * (N / 4) + (col0 / 4);

    #pragma unroll 4
    for (int r = 0; r < ROWS_PER_BLK; ++r) {
        const float4* rp = base + (size_t)r * (N / 4);
        float4 a = __ldcs(rp + t);            // streaming: don't pollute L2
        float4 b = __ldcs(rp + t + THREADS);

        c0.x += a.x; c0.y += a.y; c0.z += a.z; c0.w += a.w;
        c1.x += b.x; c1.y += b.y; c1.z += b.z; c1.w += b.w;

        // per-thread row partial -> smem; block-reduced after the loop
        s_part[r][t] = (a.x + a.y) + (a.z + a.w) + (b.x + b.y) + (b.z + b.w);
    }

    // Column partials: unique writer per (rb, col) -> plain stores, no atomics
    float4* cp = reinterpret_cast<float4*>(g_colpart + (size_t)rb * N + col0);
    cp[t]           = c0;
    cp[t + THREADS] = c1;

    __syncthreads();

    // Row reduction: 8 threads per row, each folds 32 smem values, then a
    // 3-level shuffle within the aligned 8-lane group.
    {
        const int r  = t >> 3;          // 0..31
        const int c0i = (t & 7) * 32;   // 0,32,...,224
        float s = 0.f;
        #pragma unroll
        for (int k = 0; k < 32; ++k) s += s_part[r][c0i + k];
        s += __shfl_xor_sync(0xffffffffu, s, 4);
        s += __shfl_xor_sync(0xffffffffu, s, 2);
        s += __shfl_xor_sync(0xffffffffu, s, 1);
        if ((t & 7) == 0) g_rowpart[cb * N + row0 + r] = s;
    }
}

// ---------------------------------------------------------------------------
// Pass 2: 32 blocks x 256 threads. Thread owns one column: fold all 256
// rb-partials (coalesced, L2-resident) + 4 row partials, |.|, then a
// deterministic block tree reduction to one scalar per block.
// ---------------------------------------------------------------------------
__global__ void __launch_bounds__(256)
combine_kernel(void)
{
    const int t = threadIdx.x;
    const int i = blockIdx.x * 256 + t;   // column 0..8191

    float cs = 0.f;
    #pragma unroll 16
    for (int rb = 0; rb < RB; ++rb)
        cs += g_colpart[(size_t)rb * N + i];

    float rs = 0.f;
    #pragma unroll
    for (int cb = 0; cb < CB; ++cb) rs += g_rowpart[cb * N + i];

    float v = fabsf(rs - cs);

    // block reduce (deterministic)
    v += __shfl_xor_sync(0xffffffffu, v, 16);
    v += __shfl_xor_sync(0xffffffffu, v, 8);
    v += __shfl_xor_sync(0xffffffffu, v, 4);
    v += __shfl_xor_sync(0xffffffffu, v, 2);
    v += __shfl_xor_sync(0xffffffffu, v, 1);

    __shared__ float sw[8];
    if ((t & 31) == 0) sw[t >> 5] = v;
    __syncthreads();

    if (t < 8) {
        float w = sw[t];
        w += __shfl_xor_sync(0x000000ffu, w, 4);
        w += __shfl_xor_sync(0x000000ffu, w, 2);
        w += __shfl_xor_sync(0x000000ffu, w, 1);
        if (t == 0) g_blocksum[blockIdx.x] = w;
    }
}

// ---------------------------------------------------------------------------
// Pass 3: single warp folds the 32 block partials.
// ---------------------------------------------------------------------------
__global__ void __launch_bounds__(32)
final_kernel(float* __restrict__ out)
{
    const int lane = threadIdx.x;
    float v = g_blocksum[lane];
    v += __shfl_xor_sync(0xffffffffu, v, 16);
    v += __shfl_xor_sync(0xffffffffu, v, 8);
    v += __shfl_xor_sync(0xffffffffu, v, 4);
    v += __shfl_xor_sync(0xffffffffu, v, 2);
    v += __shfl_xor_sync(0xffffffffu, v, 1);
    if (lane == 0) out[0] = v;
}

extern "C" void kernel_launch(void* const* d_in, const int* in_sizes, int n_in,
                              void* d_out, int out_size)
{
    (void)in_sizes; (void)n_in; (void)out_size;
    const float* flow = (const float*)d_in[0];
    float* out = (float*)d_out;

    tile_kernel<<<dim3(CB, RB), THREADS>>>(flow);
    combine_kernel<<<NBLK2, 256>>>();
    final_kernel<<<1, 32>>>(out);
}

// round 4
// speedup vs baseline: 1.3998x; 1.3998x over previous
#include <cuda_runtime.h>

#define N 8192
#define ROWS_PER_BLK 32
#define COLS_PER_BLK 1024
#define CB 8      /* column tiles: 8192/1024 */
#define RB 256    /* row tiles:    8192/32   */
#define THREADS 256
#define CHUNKS 8  /* epilogue stage-1 chunks over RB */

// Scratch (no device allocation allowed -> __device__ globals)
__device__ float g_rowpart[CB * N];      // [cb][row]  partial row sums (256 KB)
__device__ float g_colpart[RB * N];      // [rb][col]  partial col sums (8 MiB)
__device__ float g_cpart2[CHUNKS * N];   // folded col partials (256 KB)
__device__ float g_blocksum[32];
__device__ int   g_cnt_group[32];
__device__ int   g_cnt_final;

// ---------------------------------------------------------------------------
// Pass 1: one block per 32x1024 tile -> 2048 blocks (fine-grained, smooths the
// wave tail). Streaming single read of the 256 MiB matrix. Per iteration:
// 1 LDG.128 + col-accum (registers) + 3-shuffle partial row reduce (to 4
// lanes) -> 4 KB smem; full row fold happens once after the loop.
// ---------------------------------------------------------------------------
__global__ void __launch_bounds__(THREADS)
tile_kernel(const float* __restrict__ flow)
{
    const int cb   = blockIdx.x;          // 0..7
    const int rb   = blockIdx.y;          // 0..255
    const int t    = threadIdx.x;         // 0..255
    const int warp = t >> 5;
    const int lane = t & 31;
    const int row0 = rb * ROWS_PER_BLK;
    const int col0 = cb * COLS_PER_BLK;

    __shared__ float s_row[ROWS_PER_BLK][32];   // [row][warp*4 + sublane] 4 KB

    float4 c0 = make_float4(0.f, 0.f, 0.f, 0.f);

    const float4* base = reinterpret_cast<const float4*>(flow)
                         + (size_t)row0 * (N / 4) + (col0 / 4);

    #pragma unroll 4
    for (int r = 0; r < ROWS_PER_BLK; ++r) {
        float4 a = __ldcs(base + (size_t)r * (N / 4) + t);   // streaming

        c0.x += a.x; c0.y += a.y; c0.z += a.z; c0.w += a.w;

        // partial row reduce: 32 lanes -> 4 partials (3 shuffles)
        float s = (a.x + a.y) + (a.z + a.w);
        s += __shfl_xor_sync(0xffffffffu, s, 16);
        s += __shfl_xor_sync(0xffffffffu, s, 8);
        s += __shfl_xor_sync(0xffffffffu, s, 4);
        if (lane < 4) s_row[r][warp * 4 + lane] = s;
    }

    // Column partials: unique writer per (rb, col) -> plain store, no atomics
    reinterpret_cast<float4*>(g_colpart + (size_t)rb * N + col0)[t] = c0;

    __syncthreads();

    // Row fold: 8 threads per row (aligned 8-lane groups).
    {
        const int r = t >> 3;
        const int j = (t & 7) * 4;
        float s = (s_row[r][j] + s_row[r][j + 1])
                + (s_row[r][j + 2] + s_row[r][j + 3]);
        s += __shfl_xor_sync(0xffffffffu, s, 4);
        s += __shfl_xor_sync(0xffffffffu, s, 2);
        s += __shfl_xor_sync(0xffffffffu, s, 1);
        if ((t & 7) == 0) g_rowpart[cb * N + row0 + r] = s;
    }
}

// ---------------------------------------------------------------------------
// Pass 2 (fused epilogue, single kernel, deterministic):
//   stage 1: 256 blocks = (32 column groups) x (8 rb-chunks); each folds 32
//            rb-partials for its 256 columns -> g_cpart2.
//   stage 2: last block per column group folds 8 chunk-partials + 8 row
//            partials, |.|, block-reduce -> g_blocksum.
//   stage 3: globally-last block folds the 32 block sums -> out, resets
//            counters for the next graph replay.
// All sums use fixed orders -> bitwise deterministic.
// ---------------------------------------------------------------------------
__global__ void __launch_bounds__(256)
epilogue_kernel(float* __restrict__ out)
{
    const int t  = threadIdx.x;
    const int bx = blockIdx.x & 31;    // column group
    const int by = blockIdx.x >> 5;    // rb chunk
    const int i  = bx * 256 + t;       // column index

    float cs = 0.f;
    #pragma unroll 8
    for (int j = 0; j < RB / CHUNKS; ++j)
        cs += g_colpart[(size_t)(by * (RB / CHUNKS) + j) * N + i];
    g_cpart2[by * N + i] = cs;

    __threadfence();
    __shared__ int s_last;
    if (t == 0) s_last = (atomicAdd(&g_cnt_group[bx], 1) == CHUNKS - 1);
    __syncthreads();
    if (!s_last) return;
    __threadfence();

    // stage 2: finish column group bx
    float rs = 0.f;
    #pragma unroll
    for (int cb = 0; cb < CB; ++cb) rs += g_rowpart[cb * N + i];
    float cs2 = 0.f;
    #pragma unroll
    for (int p = 0; p < CHUNKS; ++p) cs2 += g_cpart2[p * N + i];

    float v = fabsf(rs - cs2);
    v += __shfl_xor_sync(0xffffffffu, v, 16);
    v += __shfl_xor_sync(0xffffffffu, v, 8);
    v += __shfl_xor_sync(0xffffffffu, v, 4);
    v += __shfl_xor_sync(0xffffffffu, v, 2);
    v += __shfl_xor_sync(0xffffffffu, v, 1);

    __shared__ float sw[8];
    if ((t & 31) == 0) sw[t >> 5] = v;
    __syncthreads();

    __shared__ int s_fin;
    if (t == 0) {
        float w = ((sw[0] + sw[1]) + (sw[2] + sw[3]))
                + ((sw[4] + sw[5]) + (sw[6] + sw[7]));
        g_blocksum[bx] = w;
        __threadfence();
        s_fin = (atomicAdd(&g_cnt_final, 1) == 31);
    }
    __syncthreads();
    if (!s_fin) return;
    __threadfence();

    // stage 3: globally last block folds 32 partials
    if (t < 32) {
        float v2 = g_blocksum[t];
        v2 += __shfl_xor_sync(0xffffffffu, v2, 16);
        v2 += __shfl_xor_sync(0xffffffffu, v2, 8);
        v2 += __shfl_xor_sync(0xffffffffu, v2, 4);
        v2 += __shfl_xor_sync(0xffffffffu, v2, 2);
        v2 += __shfl_xor_sync(0xffffffffu, v2, 1);
        if (t == 0) {
            out[0] = v2;
            g_cnt_final = 0;
            #pragma unroll
            for (int k = 0; k < 32; ++k) g_cnt_group[k] = 0;
        }
    }
}

extern "C" void kernel_launch(void* const* d_in, const int* in_sizes, int n_in,
                              void* d_out, int out_size)
{
    (void)in_sizes; (void)n_in; (void)out_size;
    const float* flow = (const float*)d_in[0];
    float* out = (float*)d_out;

    tile_kernel<<<dim3(CB, RB), THREADS>>>(flow);
    epilogue_kernel<<<32 * CHUNKS, 256>>>(out);
}